// round 4
// baseline (speedup 1.0000x reference)
#include <cuda_runtime.h>

// ActiveParticles step, N=4096.
// Inputs: positions[N,2] f32, orientations[N,2] f32, Deltas[1] f32,
//         rot_noise[N] f32, trans_noise[N,2] f32.
// Output: [5, N, 2] f32 = {new_p, new_u, orientation_sums, leftturns, rightturns}.

#define NMAX 4096

static __device__ float2 g_cms;
static __device__ float4 g_pu[NMAX];          // (p.x, p.y, u.x, u.y)
static __device__ float4 g_nsr[NMAX];         // (nr, srx, sry, pad)
static __device__ float2 g_os[NMAX];          // (osx, osy)
static __device__ float4 g_posA4[NMAX / 2];   // positions ping (float2 pairs)
static __device__ float4 g_posB4[NMAX / 2];   // positions pong

__device__ __forceinline__ float wsum(float v) {
#pragma unroll
    for (int o = 16; o; o >>= 1) v += __shfl_xor_sync(0xffffffffu, v, o);
    return v;
}

__device__ __forceinline__ float anglewrap(float diff) {
    const float PI_F = 3.1415927410125732f;
    if (diff <= -PI_F) diff = diff - PI_F * floorf(diff / PI_F);  // jnp.mod(diff, PI)
    if (diff >= PI_F) diff -= 2.0f * PI_F;
    return diff;
}

__device__ __forceinline__ float anglediff(float ax, float ay, float bx, float by) {
    return anglewrap(atan2f(ay, ax) - atan2f(by, bx));
}

// ------------- prep: pack (p,u) -> g_pu; block 0 computes mean(p) -----------------
__global__ void prep_kernel(const float2* __restrict__ p, const float2* __restrict__ u, int n) {
    int i = blockIdx.x * blockDim.x + threadIdx.x;
    if (i < n) {
        float2 pp = p[i], uu = u[i];
        g_pu[i] = make_float4(pp.x, pp.y, uu.x, uu.y);
    }
    if (blockIdx.x == 0) {
        __shared__ float2 sh[32];
        float sx = 0.f, sy = 0.f;
        for (int j = threadIdx.x; j < n; j += blockDim.x) {
            float2 v = p[j];
            sx += v.x; sy += v.y;
        }
        sx = wsum(sx); sy = wsum(sy);
        int lane = threadIdx.x & 31, w = threadIdx.x >> 5;
        if (lane == 0) sh[w] = make_float2(sx, sy);
        __syncthreads();
        if (w == 0) {
            int nw = blockDim.x >> 5;
            float2 v = (lane < nw) ? sh[lane] : make_float2(0.f, 0.f);
            float ax = wsum(v.x), ay = wsum(v.y);
            if (lane == 0) {
                float inv = 1.0f / fmaxf((float)n, 1.0f);   // max(n_a,1), n_a = n
                g_cms = make_float2(ax * inv, ay * inv);
            }
        }
    }
}

// ---------------- main pairwise pass ----------------------------------------------
// Block = 256 = 8 warps; 4 particles/block. Warp w: g = w>>2 selects particle pair
// (i0 = blk*4 + 2g, i1 = i0+1), s = w&3 selects quarter of j-range. Each j load
// serves 2 pairs. Grid = n/4.
__global__ void __launch_bounds__(256, 6) main_pair_kernel(int n) {
    __shared__ float red[8][10];

    const int w    = threadIdx.x >> 5;
    const int lane = threadIdx.x & 31;
    const int g    = w >> 2;
    const int s    = w & 3;
    const int i0   = blockIdx.x * 4 + g * 2;
    const int i1   = i0 + 1;

    const float4 m0 = g_pu[i0];
    const float4 m1 = g_pu[i1];

    const float RR2  = (float)(8e-6 * 8e-6);
    const float ROCf = (float)(2.5e-5 + 3.15e-6);
    const float ROC2 = ROCf * ROCf;

    float nr0 = 0.f, sx0 = 0.f, sy0 = 0.f, ox0 = 0.f, oy0 = 0.f;
    float nr1 = 0.f, sx1 = 0.f, sy1 = 0.f, ox1 = 0.f, oy1 = 0.f;

    const int q = n >> 2;                        // 1024
    for (int base = s * q; base < (s + 1) * q; base += 64) {
        float4 a0 = g_pu[base + lane];
        float4 a1 = g_pu[base + lane + 32];
#pragma unroll
        for (int k = 0; k < 2; k++) {
            float4 a = (k == 0) ? a0 : a1;
            float dxA = a.x - m0.x, dyA = a.y - m0.y;
            float dxB = a.x - m1.x, dyB = a.y - m1.y;
            float d2A = fmaf(dxA, dxA, dyA * dyA);
            float d2B = fmaf(dxB, dxB, dyB * dyB);
            if ((d2A <= ROC2) || (d2B <= ROC2)) {            // rare
                if (d2A <= ROC2) {
                    ox0 += a.z; oy0 += a.w;                  // mask_ro (incl. j==i)
                    if (d2A <= RR2 && d2A > 0.f) {           // inside_Rr, j!=i
                        float c = dxA * a.z + dyA * a.w;
                        float cs = a.z * dyA - a.w * dxA;
                        if (!(c <= 0.0f && cs >= 0.0f)) { nr0 += 1.f; sx0 += a.x; sy0 += a.y; }
                    }
                }
                if (d2B <= ROC2) {
                    ox1 += a.z; oy1 += a.w;
                    if (d2B <= RR2 && d2B > 0.f) {
                        float c = dxB * a.z + dyB * a.w;
                        float cs = a.z * dyB - a.w * dxB;
                        if (!(c <= 0.0f && cs >= 0.0f)) { nr1 += 1.f; sx1 += a.x; sy1 += a.y; }
                    }
                }
            }
        }
    }

    nr0 = wsum(nr0); sx0 = wsum(sx0); sy0 = wsum(sy0); ox0 = wsum(ox0); oy0 = wsum(oy0);
    nr1 = wsum(nr1); sx1 = wsum(sx1); sy1 = wsum(sy1); ox1 = wsum(ox1); oy1 = wsum(oy1);
    if (lane == 0) {
        red[w][0] = nr0; red[w][1] = sx0; red[w][2] = sy0; red[w][3] = ox0; red[w][4] = oy0;
        red[w][5] = nr1; red[w][6] = sx1; red[w][7] = sy1; red[w][8] = ox1; red[w][9] = oy1;
    }
    __syncthreads();

    if (threadIdx.x < 4) {
        const int qq  = threadIdx.x;             // particle 0..3 in block
        const int gg  = qq >> 1;
        const int off = (qq & 1) * 5;
        float v0 = 0.f, v1 = 0.f, v2 = 0.f, v3 = 0.f, v4 = 0.f;
#pragma unroll
        for (int ss = 0; ss < 4; ss++) {
            v0 += red[gg * 4 + ss][off + 0];
            v1 += red[gg * 4 + ss][off + 1];
            v2 += red[gg * 4 + ss][off + 2];
            v3 += red[gg * 4 + ss][off + 3];
            v4 += red[gg * 4 + ss][off + 4];
        }
        const int ii = blockIdx.x * 4 + qq;
        g_nsr[ii] = make_float4(v0, v1, v2, 0.f);
        g_os[ii]  = make_float2(v3, v4);
    }
}

// ---------------- epilogue: per-particle math, 1 thread / particle ----------------
__global__ void epilogue_kernel(const float* __restrict__ deltas,
                                const float* __restrict__ rnoise,
                                const float* __restrict__ tnoise_,
                                float* __restrict__ out, int n) {
    const int i = blockIdx.x * blockDim.x + threadIdx.x;
    if (i >= n) return;
    const float2* tn = (const float2*)tnoise_;

    const float4 m = g_pu[i];
    const float px = m.x, py = m.y, ux = m.z, uy = m.w;
    const float4 ns = g_nsr[i];
    const float2 os = g_os[i];
    const float nrT = ns.x, srxT = ns.y, sryT = ns.z;
    const float osxT = os.x, osyT = os.y;

    float sgn = (nrT > 0.f) ? 1.0f : 0.0f;
    float invr = 1.0f / fmaxf(nrT, 1.0f);
    float dax = -(srxT * invr - px * sgn);
    float day = -(sryT * invr - py * sgn);

    float2 cms = g_cms;
    float Psx = cms.x - px;                      // sign(n_a) == 1
    float Psy = cms.y - py;

    float Delta = __ldg(&deltas[0]);
    float cd = cosf(Delta), sd = sinf(Delta);
    float lx = Psx * cd - Psy * sd, ly = Psx * sd + Psy * cd;    // Ps*e^{+iD}
    float rx = Psx * cd + Psy * sd, ry = Psy * cd - Psx * sd;    // Ps*e^{-iD}

    const float EPSF = 1e-14f;
    float nb  = fmaxf(sqrtf(osxT * osxT + osyT * osyT + 1e-30f), EPSF);
    float naL = fmaxf(sqrtf(lx * lx + ly * ly + 1e-30f), EPSF);
    float naR = fmaxf(sqrtf(rx * rx + ry * ry + 1e-30f), EPSF);
    float csL = (lx * osxT + ly * osyT) / (naL * nb);
    float csR = (rx * osxT + ry * osyT) / (naR * nb);
    bool left_closer = (csL >= csR);
    float bx = left_closer ? lx : rx;
    float by = left_closer ? ly : ry;

    float d_abs = sqrtf(dax * dax + day * day);
    float ang;
    if (d_abs > 0.f) {
        ang = anglediff(dax, day, ux, uy);
    } else {
        float babs = sqrtf(bx * bx + by * by);
        float bsx = (babs > 0.f) ? bx : 1.0f;
        float bsy = (babs > 0.f) ? by : 0.0f;
        ang = anglediff(bsx, bsy, ux, uy);
    }

    const float C1   = (float)(0.2 * 25.0 * 0.0028);     // dt*Gamma*DR
    const float S2DR = (float)0.07483314773547883;       // sqrt(2*DR)
    const float SDT  = (float)0.4472135954999579;        // sqrt(dt)
    float phi = C1 * sinf(ang) + rnoise[i] * S2DR * SDT;
    float cr = cosf(phi), sr = sinf(phi);
    float nux = ux * cr - uy * sr;
    float nuy = ux * sr + uy * cr;

    const float DTV = (float)(0.2 * 5e-7);
    const float CSH = (float)0.7071067811865476;         // sqrt(0.5)
    const float C2T = (float)1.6733200530681511e-07;     // sqrt(2*DT_trans)
    float2 t = __ldg(&tn[i]);
    float tx = DTV * ux + ((t.x * CSH) * C2T) * SDT;
    float ty = DTV * uy + ((t.y * CSH) * C2T) * SDT;

    ((float2*)g_posA4)[i] = make_float2(px + tx, py + ty);
    int b = 2 * n;
    out[1 * b + 2 * i + 0] = nux;  out[1 * b + 2 * i + 1] = nuy;
    out[2 * b + 2 * i + 0] = osxT; out[2 * b + 2 * i + 1] = osyT;
    out[3 * b + 2 * i + 0] = lx;   out[3 * b + 2 * i + 1] = ly;
    out[4 * b + 2 * i + 0] = rx;   out[4 * b + 2 * i + 1] = ry;
}

// ---------------- collision sweep -------------------------------------------------
// Same tiling: warp = 2 particles x quarter j-range; 16 pair-tests per lane-iter
// behind ONE branch. pass 0: A->B, 1: B->A, 2: A->out_final.
__global__ void __launch_bounds__(256, 7) collide_kernel(int pass, float2* __restrict__ out_final, int n) {
    const float4* __restrict__ src4 = (pass == 1) ? g_posB4 : g_posA4;
    float2* dst = (pass == 0) ? (float2*)g_posB4 : (pass == 1) ? (float2*)g_posA4 : out_final;
    __shared__ float red[8][4];

    const int w    = threadIdx.x >> 5;
    const int lane = threadIdx.x & 31;
    const int g    = w >> 2;
    const int s    = w & 3;
    const int i0   = blockIdx.x * 4 + g * 2;
    const int i1   = i0 + 1;

    const float2 p0 = ((const float2*)src4)[i0];
    const float2 p1 = ((const float2*)src4)[i1];
    const float TH2 = (float)(2.0 * 3.15e-6) * (float)(2.0 * 3.15e-6);
    const float C21 = (float)(2.1 * 3.15e-6);
    const unsigned uTH2 = __float_as_uint(TH2);

    float mv0x = 0.f, mv0y = 0.f, mv1x = 0.f, mv1y = 0.f;

    const int qf = n >> 3;                       // float4s per quarter = 512
    for (int fb = s * qf; fb < (s + 1) * qf; fb += 128) {
        float4 a0 = src4[fb + lane];
        float4 a1 = src4[fb + lane + 32];
        float4 a2 = src4[fb + lane + 64];
        float4 a3 = src4[fb + lane + 96];

        // hit iff 0 < d2 <= TH2  <=>  (bits(d2) - 1) <U bits(TH2)
        bool any = false;
#pragma unroll
        for (int k = 0; k < 4; k++) {
            float4 v = (k == 0) ? a0 : (k == 1) ? a1 : (k == 2) ? a2 : a3;
            float dx, dy, d2;
            dx = v.x - p0.x; dy = v.y - p0.y; d2 = fmaf(dx, dx, dy * dy);
            any |= ((__float_as_uint(d2) - 1u) < uTH2);
            dx = v.z - p0.x; dy = v.w - p0.y; d2 = fmaf(dx, dx, dy * dy);
            any |= ((__float_as_uint(d2) - 1u) < uTH2);
            dx = v.x - p1.x; dy = v.y - p1.y; d2 = fmaf(dx, dx, dy * dy);
            any |= ((__float_as_uint(d2) - 1u) < uTH2);
            dx = v.z - p1.x; dy = v.w - p1.y; d2 = fmaf(dx, dx, dy * dy);
            any |= ((__float_as_uint(d2) - 1u) < uTH2);
        }
        if (any) {                               // rare (~2% of warp-iterations)
#pragma unroll
            for (int k = 0; k < 4; k++) {
                float4 v = (k == 0) ? a0 : (k == 1) ? a1 : (k == 2) ? a2 : a3;
#pragma unroll
                for (int half = 0; half < 2; half++) {
                    float jx = half ? v.z : v.x;
                    float jy = half ? v.w : v.y;
                    {
                        float dx = jx - p0.x, dy = jy - p0.y;
                        float d2 = fmaf(dx, dx, dy * dy);
                        if ((__float_as_uint(d2) - 1u) < uTH2) {
                            float ab = sqrtf(d2);
                            float sc = (C21 - ab) * 0.5f / ab;
                            mv0x += dx * sc; mv0y += dy * sc;
                        }
                    }
                    {
                        float dx = jx - p1.x, dy = jy - p1.y;
                        float d2 = fmaf(dx, dx, dy * dy);
                        if ((__float_as_uint(d2) - 1u) < uTH2) {
                            float ab = sqrtf(d2);
                            float sc = (C21 - ab) * 0.5f / ab;
                            mv1x += dx * sc; mv1y += dy * sc;
                        }
                    }
                }
            }
        }
    }

    mv0x = wsum(mv0x); mv0y = wsum(mv0y); mv1x = wsum(mv1x); mv1y = wsum(mv1y);
    if (lane == 0) {
        red[w][0] = mv0x; red[w][1] = mv0y; red[w][2] = mv1x; red[w][3] = mv1y;
    }
    __syncthreads();
    if (threadIdx.x < 4) {
        const int qq  = threadIdx.x;
        const int gg  = qq >> 1;
        const int off = (qq & 1) * 2;
        float mx = 0.f, my = 0.f;
#pragma unroll
        for (int ss = 0; ss < 4; ss++) {
            mx += red[gg * 4 + ss][off + 0];
            my += red[gg * 4 + ss][off + 1];
        }
        const int ii = blockIdx.x * 4 + qq;
        float2 pv = ((const float2*)src4)[ii];
        dst[ii] = make_float2(pv.x - mx, pv.y - my);
    }
}

extern "C" void kernel_launch(void* const* d_in, const int* in_sizes, int n_in,
                              void* d_out, int out_size) {
    const float* pos = (const float*)d_in[0];
    const float* ori = (const float*)d_in[1];
    const float* del = (const float*)d_in[2];
    const float* rno = (const float*)d_in[3];
    const float* tno = (const float*)d_in[4];
    float* out = (float*)d_out;
    const int n = in_sizes[3];                   // rot_noise has N elements

    const int blocks = n / 4;                    // 4 particles per 256-thread block

    prep_kernel<<<(n + 1023) / 1024, 1024>>>((const float2*)pos, (const float2*)ori, n);
    main_pair_kernel<<<blocks, 256>>>(n);
    epilogue_kernel<<<(n + 255) / 256, 256>>>(del, rno, tno, out, n);
    collide_kernel<<<blocks, 256>>>(0, nullptr, n);
    collide_kernel<<<blocks, 256>>>(1, nullptr, n);
    collide_kernel<<<blocks, 256>>>(2, (float2*)out, n);
}

// round 5
// speedup vs baseline: 3.1219x; 3.1219x over previous
#include <cuda_runtime.h>

// ActiveParticles step, N=4096.
// Inputs: positions[N,2] f32, orientations[N,2] f32, Deltas[1] f32,
//         rot_noise[N] f32, trans_noise[N,2] f32.
// Output: [5, N, 2] f32 = {new_p, new_u, orientation_sums, leftturns, rightturns}.

#define NMAX 4096

static __device__ float2 g_cms;
static __device__ float4 g_pu[NMAX];          // (p.x, p.y, u.x, u.y)
static __device__ float4 g_posA4[NMAX / 2];   // positions ping (float2 pairs)
static __device__ float4 g_posB4[NMAX / 2];   // positions pong

__device__ __forceinline__ float wsum(float v) {
#pragma unroll
    for (int o = 16; o; o >>= 1) v += __shfl_xor_sync(0xffffffffu, v, o);
    return v;
}

__device__ __forceinline__ float anglewrap(float diff) {
    const float PI_F = 3.1415927410125732f;
    if (diff <= -PI_F) diff = diff - PI_F * floorf(diff / PI_F);  // jnp.mod(diff, PI)
    if (diff >= PI_F) diff -= 2.0f * PI_F;
    return diff;
}

__device__ __forceinline__ float anglediff(float ax, float ay, float bx, float by) {
    return anglewrap(atan2f(ay, ax) - atan2f(by, bx));
}

// ------------- prep: pack (p,u) -> g_pu; block 0 computes mean(p) -----------------
__global__ void prep_kernel(const float2* __restrict__ p, const float2* __restrict__ u, int n) {
    int i = blockIdx.x * blockDim.x + threadIdx.x;
    if (i < n) {
        float2 pp = p[i], uu = u[i];
        g_pu[i] = make_float4(pp.x, pp.y, uu.x, uu.y);
    }
    if (blockIdx.x == 0) {
        __shared__ float2 sh[32];
        float sx = 0.f, sy = 0.f;
        for (int j = threadIdx.x; j < n; j += blockDim.x) {
            float2 v = p[j];
            sx += v.x; sy += v.y;
        }
        sx = wsum(sx); sy = wsum(sy);
        int lane = threadIdx.x & 31, w = threadIdx.x >> 5;
        if (lane == 0) sh[w] = make_float2(sx, sy);
        __syncthreads();
        if (w == 0) {
            int nw = blockDim.x >> 5;
            float2 v = (lane < nw) ? sh[lane] : make_float2(0.f, 0.f);
            float ax = wsum(v.x), ay = wsum(v.y);
            if (lane == 0) {
                float inv = 1.0f / fmaxf((float)n, 1.0f);   // max(n_a,1), n_a = n
                g_cms = make_float2(ax * inv, ay * inv);
            }
        }
    }
}

// ---------------- main pairwise pass: one warp per particle, 8-wide MLP -----------
// Block = 128 threads = 4 warps = 4 particles. Grid = n/4.
__global__ void __launch_bounds__(128) main_kernel(
        const float* __restrict__ deltas, const float* __restrict__ rnoise,
        const float* __restrict__ tnoise_, float* __restrict__ out, int n) {
    const float2* tn = (const float2*)tnoise_;

    const int lane = threadIdx.x & 31;
    const int i = blockIdx.x * 4 + (threadIdx.x >> 5);

    const float4 me = g_pu[i];
    const float pix = me.x, piy = me.y, uix = me.z, uiy = me.w;

    const float RR2  = (float)(8e-6 * 8e-6);
    const float ROCf = (float)(2.5e-5 + 3.15e-6);
    const float ROC2 = ROCf * ROCf;
    const unsigned uRR2 = __float_as_uint(RR2);

    float nr = 0.f, srx = 0.f, sry = 0.f, osx = 0.f, osy = 0.f;

    // N multiple of 256: 8 independent float4 loads per lane per outer iteration.
    for (int base = 0; base < n; base += 256) {
        float4 a0 = g_pu[base + lane];
        float4 a1 = g_pu[base + lane + 32];
        float4 a2 = g_pu[base + lane + 64];
        float4 a3 = g_pu[base + lane + 96];
        float4 a4 = g_pu[base + lane + 128];
        float4 a5 = g_pu[base + lane + 160];
        float4 a6 = g_pu[base + lane + 192];
        float4 a7 = g_pu[base + lane + 224];
#pragma unroll
        for (int k = 0; k < 8; k++) {
            float4 a = (k == 0) ? a0 : (k == 1) ? a1 : (k == 2) ? a2 : (k == 3) ? a3
                     : (k == 4) ? a4 : (k == 5) ? a5 : (k == 6) ? a6 : a7;
            float dx = a.x - pix, dy = a.y - piy;
            float d2 = fmaf(dx, dx, dy * dy);
            if (d2 <= ROC2) {                         // rare; includes j==i
                osx += a.z; osy += a.w;               // mask_ro
                // inside_Rr excl. self: 0 < d2 <= RR2  <=>  bits(d2)-1 <u bits(RR2)
                if ((__float_as_uint(d2) - 1u) < uRR2) {
                    // in_front: wrap(angle(dir)-angle(u_j)) < pi/2
                    //   <=> !(dot<=0 && cross>=0)
                    float c = dx * a.z + dy * a.w;
                    float s = a.z * dy - a.w * dx;
                    if (!(c <= 0.0f && s >= 0.0f)) { nr += 1.f; srx += a.x; sry += a.y; }
                }
            }
        }
    }
    nr = wsum(nr); srx = wsum(srx); sry = wsum(sry); osx = wsum(osx); osy = wsum(osy);

    // ---- per-particle epilogue (all lanes redundant, lane 0 writes) ----
    float sgn = (nr > 0.f) ? 1.0f : 0.0f;
    float invr = 1.0f / fmaxf(nr, 1.0f);
    float dax = -(srx * invr - pix * sgn);
    float day = -(sry * invr - piy * sgn);

    float2 cms = g_cms;
    float Psx = cms.x - pix;                          // sign(n_a) == 1
    float Psy = cms.y - piy;

    float Delta = __ldg(&deltas[0]);
    float cd = cosf(Delta), sd = sinf(Delta);
    float lx = Psx * cd - Psy * sd, ly = Psx * sd + Psy * cd;  // Ps*e^{+iD}
    float rx = Psx * cd + Psy * sd, ry = Psy * cd - Psx * sd;  // Ps*e^{-iD}

    const float EPSF = 1e-14f;
    float nb  = fmaxf(sqrtf(osx * osx + osy * osy + 1e-30f), EPSF);
    float naL = fmaxf(sqrtf(lx * lx + ly * ly + 1e-30f), EPSF);
    float naR = fmaxf(sqrtf(rx * rx + ry * ry + 1e-30f), EPSF);
    float csL = (lx * osx + ly * osy) / (naL * nb);
    float csR = (rx * osx + ry * osy) / (naR * nb);
    bool left_closer = (csL >= csR);
    float bx = left_closer ? lx : rx;
    float by = left_closer ? ly : ry;

    float d_abs = sqrtf(dax * dax + day * day);
    float ang;
    if (d_abs > 0.f) {
        ang = anglediff(dax, day, uix, uiy);
    } else {
        float babs = sqrtf(bx * bx + by * by);
        float bsx = (babs > 0.f) ? bx : 1.0f;
        float bsy = (babs > 0.f) ? by : 0.0f;
        ang = anglediff(bsx, bsy, uix, uiy);
    }

    const float C1   = (float)(0.2 * 25.0 * 0.0028);  // dt*Gamma*DR
    const float S2DR = (float)0.07483314773547883;    // sqrt(2*DR)
    const float SDT  = (float)0.4472135954999579;     // sqrt(dt)
    float phi = C1 * sinf(ang) + rnoise[i] * S2DR * SDT;
    float cr = cosf(phi), sr = sinf(phi);
    float nux = uix * cr - uiy * sr;
    float nuy = uix * sr + uiy * cr;

    const float DTV = (float)(0.2 * 5e-7);
    const float CSH = (float)0.7071067811865476;      // sqrt(0.5)
    const float C2T = (float)1.6733200530681511e-07;  // sqrt(2*DT_trans)
    float2 t = __ldg(&tn[i]);
    float tx = DTV * uix + ((t.x * CSH) * C2T) * SDT;
    float ty = DTV * uiy + ((t.y * CSH) * C2T) * SDT;

    if (lane == 0) {
        ((float2*)g_posA4)[i] = make_float2(pix + tx, piy + ty);
        int b = 2 * n;
        out[1 * b + 2 * i + 0] = nux;  out[1 * b + 2 * i + 1] = nuy;
        out[2 * b + 2 * i + 0] = osx;  out[2 * b + 2 * i + 1] = osy;
        out[3 * b + 2 * i + 0] = lx;   out[3 * b + 2 * i + 1] = ly;
        out[4 * b + 2 * i + 0] = rx;   out[4 * b + 2 * i + 1] = ry;
    }
}

// ---------------- collision sweep: one warp per particle, 8-wide MLP --------------
// pass 0: A->B, 1: B->A, 2: A->out_final.
__global__ void __launch_bounds__(128) collide_kernel(int pass, float2* __restrict__ out_final, int n) {
    const float4* __restrict__ src4 = (pass == 1) ? g_posB4 : g_posA4;
    float2* dst = (pass == 0) ? (float2*)g_posB4 : (pass == 1) ? (float2*)g_posA4 : out_final;

    const int lane = threadIdx.x & 31;
    const int i = blockIdx.x * 4 + (threadIdx.x >> 5);

    const float2 pi = ((const float2*)src4)[i];
    const float TH2 = (float)(2.0 * 3.15e-6) * (float)(2.0 * 3.15e-6);
    const float C21 = (float)(2.1 * 3.15e-6);
    const unsigned uTH2 = __float_as_uint(TH2);

    float mvx = 0.f, mvy = 0.f;
    // n/2 float4s total; 8 loads (16 j) per lane per outer iteration; n mult of 512.
    for (int fb = 0; fb < (n >> 1); fb += 256) {
        float4 q0 = src4[fb + lane];
        float4 q1 = src4[fb + lane + 32];
        float4 q2 = src4[fb + lane + 64];
        float4 q3 = src4[fb + lane + 96];
        float4 q4 = src4[fb + lane + 128];
        float4 q5 = src4[fb + lane + 160];
        float4 q6 = src4[fb + lane + 192];
        float4 q7 = src4[fb + lane + 224];
#pragma unroll
        for (int k = 0; k < 8; k++) {
            float4 v = (k == 0) ? q0 : (k == 1) ? q1 : (k == 2) ? q2 : (k == 3) ? q3
                     : (k == 4) ? q4 : (k == 5) ? q5 : (k == 6) ? q6 : q7;
            float dxa = v.x - pi.x, dya = v.y - pi.y;
            float dxb = v.z - pi.x, dyb = v.w - pi.y;
            float d2a = fmaf(dxa, dxa, dya * dya);
            float d2b = fmaf(dxb, dxb, dyb * dyb);
            // hit iff 0 < d2 <= TH2 (d2==0 <=> self)
            bool hitA = (__float_as_uint(d2a) - 1u) < uTH2;
            bool hitB = (__float_as_uint(d2b) - 1u) < uTH2;
            if (hitA || hitB) {                        // rare
                if (hitA) {
                    float ab = sqrtf(d2a);
                    float sc = (C21 - ab) * 0.5f / ab;
                    mvx += dxa * sc; mvy += dya * sc;
                }
                if (hitB) {
                    float ab = sqrtf(d2b);
                    float sc = (C21 - ab) * 0.5f / ab;
                    mvx += dxb * sc; mvy += dyb * sc;
                }
            }
        }
    }
    mvx = wsum(mvx); mvy = wsum(mvy);
    if (lane == 0) dst[i] = make_float2(pi.x - mvx, pi.y - mvy);
}

extern "C" void kernel_launch(void* const* d_in, const int* in_sizes, int n_in,
                              void* d_out, int out_size) {
    const float* pos = (const float*)d_in[0];
    const float* ori = (const float*)d_in[1];
    const float* del = (const float*)d_in[2];
    const float* rno = (const float*)d_in[3];
    const float* tno = (const float*)d_in[4];
    float* out = (float*)d_out;
    const int n = in_sizes[3];                  // rot_noise has N elements

    const int blocks = n / 4;                   // 4 warps/block, 1 particle/warp

    prep_kernel<<<(n + 1023) / 1024, 1024>>>((const float2*)pos, (const float2*)ori, n);
    main_kernel<<<blocks, 128>>>(del, rno, tno, out, n);
    collide_kernel<<<blocks, 128>>>(0, nullptr, n);
    collide_kernel<<<blocks, 128>>>(1, nullptr, n);
    collide_kernel<<<blocks, 128>>>(2, (float2*)out, n);
}